// round 6
// baseline (speedup 1.0000x reference)
#include <cuda_runtime.h>
#include <math.h>
#include <stdint.h>

constexpr int B  = 64;
constexpr int T  = 2048;
constexpr int D  = 128;
constexpr int H  = 256;
constexpr int H2 = 512;
constexpr float EPS = 1e-5f;

constexpr int NCTA = 128;   // 16 col-groups x 8 batch-groups
constexpr int NT   = 512;   // 16 warps -> 4 per SMSP
constexpr int GR   = 8;     // batch groups
constexpr int BPG  = 8;     // rows per group

// ---------------- device scratch ----------------
__device__ float g_xproj[(size_t)T * GR * 4 * H * BPG]; // [t][bg][g][n][b']
__device__ float g_h[GR * H * BPG];                     // [(bg*H + n)*8 + b']
__device__ float g_c[GR * H * BPG];
__device__ float g_part[(size_t)GR * 16 * H * BPG];     // [bg][j][n][b']
__device__ unsigned int g_barr[GR * 32];                // one 128B line per group

__global__ void k_init() { if (threadIdx.x < GR * 32) g_barr[threadIdx.x] = 0u; }
__global__ void k_dummy() { }   // ncu launch-index alignment

// ---------------- packed f32x2 helpers (sm_103a) ----------------
__device__ __forceinline__ void ffma2(uint64_t& a, uint64_t x, uint64_t y) {
    asm("fma.rn.f32x2 %0, %1, %2, %0;" : "+l"(a) : "l"(x), "l"(y));
}
__device__ __forceinline__ float2 unpk(uint64_t a) {
    float2 f;
    asm("mov.b64 {%0, %1}, %2;" : "=f"(f.x), "=f"(f.y) : "l"(a));
    return f;
}

// ---------------- phase 1: input-projection GEMM ----------------
__global__ void __launch_bounds__(256) k_xproj(
    const float* __restrict__ x,
    const float* __restrict__ W0, const float* __restrict__ W1,
    const float* __restrict__ W2, const float* __restrict__ W3,
    const float* __restrict__ b0, const float* __restrict__ b1,
    const float* __restrict__ b2, const float* __restrict__ b3)
{
    extern __shared__ float sm[];
    float* As = sm;
    float* Bs = sm + 128 * 68;

    const int tid = threadIdx.x;
    const int t  = blockIdx.y;
    const int nb = blockIdx.x;
    const int g  = nb >> 2;
    const int nbase = (nb & 3) * 64;

    const float* W    = (g == 0) ? W0 : (g == 1) ? W1 : (g == 2) ? W2 : W3;
    const float* bias = (g == 0) ? b0 : (g == 1) ? b1 : (g == 2) ? b2 : b3;

    for (int idx = tid; idx < 64 * 128; idx += 256) {
        int bb = idx >> 7, d = idx & 127;
        As[d * 68 + bb] = x[(size_t)bb * T * D + (size_t)t * D + d];
    }
    for (int idx = tid; idx < 128 * 64; idx += 256) {
        int d = idx >> 6, np = idx & 63;
        Bs[d * 68 + np] = W[(size_t)d * H + nbase + np];
    }
    __syncthreads();

    const int tx = tid & 15, ty = tid >> 4;
    const int bb0 = ty * 4, np0 = tx * 4;

    float acc[4][4];
#pragma unroll
    for (int i = 0; i < 4; i++)
#pragma unroll
        for (int j = 0; j < 4; j++) acc[i][j] = 0.f;

#pragma unroll 8
    for (int k = 0; k < 128; k++) {
        float4 av = *(const float4*)&As[k * 68 + bb0];
        float4 wv = *(const float4*)&Bs[k * 68 + np0];
        acc[0][0] += av.x * wv.x; acc[0][1] += av.x * wv.y; acc[0][2] += av.x * wv.z; acc[0][3] += av.x * wv.w;
        acc[1][0] += av.y * wv.x; acc[1][1] += av.y * wv.y; acc[1][2] += av.y * wv.z; acc[1][3] += av.y * wv.w;
        acc[2][0] += av.z * wv.x; acc[2][1] += av.z * wv.y; acc[2][2] += av.z * wv.z; acc[2][3] += av.z * wv.w;
        acc[3][0] += av.w * wv.x; acc[3][1] += av.w * wv.y; acc[3][2] += av.w * wv.z; acc[3][3] += av.w * wv.w;
    }

#pragma unroll
    for (int j = 0; j < 4; j++) {
        int n = nbase + np0 + j;
        float bv = __ldg(&bias[n]);
#pragma unroll
        for (int i = 0; i < 4; i++) {
            int bb = bb0 + i;
            g_xproj[((((size_t)t * GR + (bb >> 3)) * 4 + g) * H + n) * BPG + (bb & 7)]
                = acc[i][j] + bv;
        }
    }
}

// ---------------- group barrier: split arrive / wait (warp-0 poll) ----------------
__device__ __forceinline__ void gsync_arrive(int bg)
{
    __syncthreads();
    if (threadIdx.x == 0)
        asm volatile("red.release.gpu.global.add.u32 [%0], 1;"
                     :: "l"(&g_barr[bg * 32]) : "memory");
}
__device__ __forceinline__ void gsync_wait(int bg, unsigned int tgt)
{
    if (threadIdx.x < 32) {
        unsigned int v;
        do {
            asm volatile("ld.acquire.gpu.global.u32 %0, [%1];"
                         : "=r"(v) : "l"(&g_barr[bg * 32]) : "memory");
        } while (v < tgt);
    }
    __syncthreads();
}

__device__ __forceinline__ float sigf(float v) { return 1.f / (1.f + expf(-v)); }

// ---------------- phase 2: persistent scan ----------------
__global__ void __launch_bounds__(NT) k_scan(
    const float* __restrict__ Ui, const float* __restrict__ Uf,
    const float* __restrict__ Uc, const float* __restrict__ Uo,
    const float* __restrict__ K1, const float* __restrict__ kb1,
    const float* __restrict__ K2, const float* __restrict__ kb2,
    const float* __restrict__ gamma, const float* __restrict__ beta,
    float* __restrict__ out, int has_hc)
{
    extern __shared__ float sm[];
    float* sU   = sm;             // [k][n'16*g4]         16384
    float* sK1  = sU  + 16384;    // [k][m'32]             8192
    float* sK2d = sK1 + 8192;     // [m'32][n256][dup2]   16384
    float* sA2  = sK2d + 16384;   // staging dup [k][b][2] 4096
    float* sRed = sA2 + 4096;     // split-K partials      4608
    float* sZp  = sRed + 4608;    // z pairs [m'][8]        256
    float* sG   = sZp + 256;      // gates [g4][128]        512
    float* sCc  = sG  + 512;      // cell state             128
    float* sMu  = sCc + 128;      // [8]
    float* sRstd= sMu + 8;        // [8]
    float* sGU  = sRstd + 8;      // [n'*4+g]                64
    float* sBU  = sGU + 64;       //                         64
    float* sSt  = sBU + 64;       // stats partials [16w][16] 256

    const int tid = threadIdx.x;
    const int cta = blockIdx.x;
    const int cg  = cta & 15;
    const int bg  = cta >> 4;
    const int n0  = cg * 16;
    const int m0  = cg * 32;
    const int b0  = bg * 8;

    // ---- preamble: weight slices into smem ----
    for (int idx = tid; idx < H * 64; idx += NT) {
        int k = idx >> 6, r = idx & 63, n = r >> 2, g = r & 3;
        const float* Up = (g == 0) ? Ui : (g == 1) ? Uf : (g == 2) ? Uc : Uo;
        sU[idx] = gamma[k] * Up[(size_t)k * H + n0 + n];
    }
    for (int idx = tid; idx < H * 32; idx += NT) {
        int k = idx >> 5, m = idx & 31;
        sK1[idx] = K1[(size_t)k * H2 + m0 + m];
    }
    for (int idx = tid; idx < 32 * H; idx += NT) {
        int m = idx >> 8, n = idx & 255;
        float w = K2[(size_t)(m0 + m) * H + n];
        sK2d[idx * 2] = w; sK2d[idx * 2 + 1] = w;
    }
    if (tid < 128) sCc[tid] = 0.f;
    __syncthreads();
    if (tid < 64) {
        int n = tid >> 2, g = tid & 3;
        const float* Up = (g == 0) ? Ui : (g == 1) ? Uf : (g == 2) ? Uc : Uo;
        float s = 0.f, bs = 0.f;
        for (int k = 0; k < H; k++) {
            s  += sU[k * 64 + tid];
            bs += beta[k] * Up[(size_t)k * H + n0 + n];
        }
        sGU[tid] = s; sBU[tid] = bs;
    }
    float rkb1 = 0.f;
    if (tid < 256) rkb1 = kb1[m0 + (tid >> 3)];
    float rkb2 = 0.f, rgam = 0.f, rbet = 0.f;
    if (tid < 128) {
        rkb2 = kb2[n0 + (tid >> 3)];
        rgam = gamma[n0 + (tid >> 3)];
        rbet = beta[n0 + (tid >> 3)];
    }
    __syncthreads();

    unsigned int tgt = 0;
    const float invH = 1.f / (float)H;

    // prefetch xproj for t = 0 (one gate value per thread)
    const int xg  = tid >> 7;          // gate 0..3
    const int xrn = (tid >> 3) & 15;   // n'
    const int xrb = tid & 7;           // b'
    float xp = g_xproj[(((size_t)0 * GR + bg) * 4 + xg) * (H * BPG)
                       + (size_t)(n0 + xrn) * BPG + xrb];

    for (int t = 0; t < T; t++) {
        float outv = 0.f;
        if (t > 0) {
            // ---- stage h duplicated (L2-direct) ----
            {
                const float4* src = (const float4*)(g_h + bg * (H * BPG));
                float4 v = __ldcg(&src[tid]);
                int n = tid >> 1, bo = (tid & 1) * 8;
                *(float4*)&sA2[n * 16 + bo]     = make_float4(v.x, v.x, v.y, v.y);
                *(float4*)&sA2[n * 16 + bo + 4] = make_float4(v.z, v.z, v.w, v.w);
            }
            __syncthreads();
            // ---- LN stats ----
            {
                float s = 0.f, s2 = 0.f;
#pragma unroll
                for (int j = 0; j < 4; j++) {
                    int flat = tid + j * 512;
                    float v = sA2[(flat >> 3) * 16 + (flat & 7) * 2];
                    s += v; s2 += v * v;
                }
                s  += __shfl_xor_sync(0xffffffffu, s, 8);
                s2 += __shfl_xor_sync(0xffffffffu, s2, 8);
                s  += __shfl_xor_sync(0xffffffffu, s, 16);
                s2 += __shfl_xor_sync(0xffffffffu, s2, 16);
                int lane = tid & 31, wp = tid >> 5;
                if (lane < 8) { sSt[wp * 16 + lane * 2] = s; sSt[wp * 16 + lane * 2 + 1] = s2; }
            }
            __syncthreads();
            if (tid < 8) {
                float ss = 0.f, qq = 0.f;
#pragma unroll
                for (int w = 0; w < 16; w++) { ss += sSt[w * 16 + tid * 2]; qq += sSt[w * 16 + tid * 2 + 1]; }
                float mu = ss * invH;
                float var = qq * invH - mu * mu;
                sMu[tid] = mu; sRstd[tid] = rsqrtf(var + EPS);
            }
            __syncthreads();
            if (tid < 128) {   // LN'd output value; STG deferred past arrive
                int bb = tid & 7, nn = tid >> 3;
                outv = (sA2[(n0 + nn) * 16 + bb * 2] - sMu[bb]) * sRstd[bb] * rgam + rbet;
            }

            // ---- P1: recurrent GEMV, 8 chunks x 32 k ----
            {
                const int chunk = tid >> 6, og = tid & 63, p = og & 3, nn = og >> 2;
                uint64_t A0 = 0, A1 = 0, A2 = 0, A3 = 0;
                const int kb = chunk * 32;
#pragma unroll 8
                for (int kk = 0; kk < 32; kk++) {
                    int k = kb + kk;
                    uint64_t H0 = *(const uint64_t*)&sA2[k * 16 + p * 2];
                    uint64_t H1 = *(const uint64_t*)&sA2[k * 16 + (p + 4) * 2];
                    const uint64_t* wp2 = (const uint64_t*)&sU[k * 64 + nn * 4];
                    uint64_t w01 = wp2[0], w23 = wp2[1];
                    ffma2(A0, H0, w01); ffma2(A1, H0, w23);
                    ffma2(A2, H1, w01); ffma2(A3, H1, w23);
                }
                int base = chunk * 576 + og * 9;
                float2 f;
                f = unpk(A0); sRed[base + 0] = f.x; sRed[base + 1] = f.y;
                f = unpk(A1); sRed[base + 2] = f.x; sRed[base + 3] = f.y;
                f = unpk(A2); sRed[base + 4] = f.x; sRed[base + 5] = f.y;
                f = unpk(A3); sRed[base + 6] = f.x; sRed[base + 7] = f.y;
            }
            __syncthreads();
        }

        // ---- gate consumer: one gate per thread ----
        {
            float pa;
            if (t > 0) {
                int og = xrn * 4 + (xrb & 3);
                int off = (xrb >> 2) * 4 + xg;
                float d = 0.f;
#pragma unroll
                for (int c = 0; c < 8; c++) d += sRed[c * 576 + og * 9 + off];
                float mu = sMu[xrb], rs = sRstd[xrb];
                pa = xp + rs * (d - mu * sGU[xrn * 4 + xg]) + sBU[xrn * 4 + xg];
            } else pa = xp;
            float v = (xg == 2) ? tanhf(pa) : sigf(pa);
            sG[xg * 128 + xrn * 8 + xrb] = v;
        }
        __syncthreads();
        if (tid < 128) {  // c update
            float cn = sG[128 + tid] * sCc[tid] + sG[tid] * sG[256 + tid];
            sCc[tid] = cn;
            __stcg(&g_c[(bg * H + n0 + (tid >> 3)) * BPG + (tid & 7)], cn);
        }
        gsync_arrive(bg);                 // barrier 1 arrive: c visible
        // overlap: deferred out STG + next-step xproj prefetch
        if (t > 0 && tid < 128) {
            int bb = tid & 7, nn = tid >> 3;
            out[((size_t)(b0 + bb) * T + (t - 1)) * H + n0 + nn] = outv;
        }
        if (t + 1 < T)
            xp = g_xproj[(((size_t)(t + 1) * GR + bg) * 4 + xg) * (H * BPG)
                         + (size_t)(n0 + xrn) * BPG + xrb];
        tgt += 16;
        gsync_wait(bg, tgt);              // barrier 1 wait

        // ---- stage c duplicated ----
        {
            const float4* src = (const float4*)(g_c + bg * (H * BPG));
            float4 v = __ldcg(&src[tid]);
            int n = tid >> 1, bo = (tid & 1) * 8;
            *(float4*)&sA2[n * 16 + bo]     = make_float4(v.x, v.x, v.y, v.y);
            *(float4*)&sA2[n * 16 + bo + 4] = make_float4(v.z, v.z, v.w, v.w);
        }
        __syncthreads();

        // ---- P2: z = tanh(c @ K1 + kb1), 16 chunks x 16 k ----
        {
            const int chunk = tid >> 5, og = tid & 31, p = og & 3, m4 = og >> 2;
            uint64_t A0 = 0, A1 = 0, A2 = 0, A3 = 0;
            const int kb = chunk * 16;
#pragma unroll 8
            for (int kk = 0; kk < 16; kk++) {
                int k = kb + kk;
                uint64_t C0 = *(const uint64_t*)&sA2[k * 16 + p * 2];
                uint64_t C1 = *(const uint64_t*)&sA2[k * 16 + (p + 4) * 2];
                const uint64_t* wp2 = (const uint64_t*)&sK1[k * 32 + m4 * 4];
                uint64_t w01 = wp2[0], w23 = wp2[1];
                ffma2(A0, C0, w01); ffma2(A1, C0, w23);
                ffma2(A2, C1, w01); ffma2(A3, C1, w23);
            }
            int base = chunk * 288 + og * 9;
            float2 f;
            f = unpk(A0); sRed[base + 0] = f.x; sRed[base + 1] = f.y;
            f = unpk(A1); sRed[base + 2] = f.x; sRed[base + 3] = f.y;
            f = unpk(A2); sRed[base + 4] = f.x; sRed[base + 5] = f.y;
            f = unpk(A3); sRed[base + 6] = f.x; sRed[base + 7] = f.y;
        }
        __syncthreads();
        if (tid < 256) {   // z consumer -> pair-interleaved sZp
            int mq = tid >> 3, bb = tid & 7;
            int og = (mq >> 2) * 4 + (bb & 3);
            int off = (bb >> 2) * 4 + (mq & 3);
            float d = 0.f;
#pragma unroll
            for (int c = 0; c < 16; c++) d += sRed[c * 288 + og * 9 + off];
            sZp[mq * 8 + (bb & 3) * 2 + (bb >> 2)] = tanhf(d + rkb1);
        }
        __syncthreads();

        // ---- P3 producer: partial ctr, split over m-halves ----
        float2 f0, f1, f2, f3;
        {
            const int n = tid & 255, mh = tid >> 8;
            uint64_t A0 = 0, A1 = 0, A2 = 0, A3 = 0;
            const int mb = mh * 16;
#pragma unroll 8
            for (int mm = 0; mm < 16; mm++) {
                int m = mb + mm;
                const uint64_t* zp = (const uint64_t*)&sZp[m * 8];
                uint64_t z0 = zp[0], z1 = zp[1], z2 = zp[2], z3 = zp[3];
                uint64_t W = *(const uint64_t*)&sK2d[(m * 256 + n) * 2];
                ffma2(A0, z0, W); ffma2(A1, z1, W);
                ffma2(A2, z2, W); ffma2(A3, z3, W);
            }
            f0 = unpk(A0); f1 = unpk(A1); f2 = unpk(A2); f3 = unpk(A3);
            if (mh == 1) {
                int base = n * 9;
                sRed[base + 0] = f0.x; sRed[base + 1] = f1.x; sRed[base + 2] = f2.x; sRed[base + 3] = f3.x;
                sRed[base + 4] = f0.y; sRed[base + 5] = f1.y; sRed[base + 6] = f2.y; sRed[base + 7] = f3.y;
            }
        }
        __syncthreads();
        if (tid < 256) {   // mh==0 combines and writes partial tile
            int n = tid, base = n * 9;
            float4 lo = make_float4(f0.x + sRed[base + 0], f1.x + sRed[base + 1],
                                    f2.x + sRed[base + 2], f3.x + sRed[base + 3]);
            float4 hi = make_float4(f0.y + sRed[base + 4], f1.y + sRed[base + 5],
                                    f2.y + sRed[base + 6], f3.y + sRed[base + 7]);
            float* gp = &g_part[(((size_t)bg * 16 + cg) * H + n) * BPG];
            __stcg((float4*)gp, lo);
            __stcg((float4*)(gp + 4), hi);
        }
        gsync_arrive(bg);  tgt += 16;  gsync_wait(bg, tgt);   // barrier 2

        // ---- P3 consumer: ctr = sum_j part ; h = o*tanh(ctr+kb2) ----
        {
            int idx = tid & 127, q = tid >> 7;
            int nn = idx >> 3, bb = idx & 7;
            float ssum = 0.f;
#pragma unroll
            for (int jj = 0; jj < 4; jj++) {
                int j = q * 4 + jj;
                ssum += __ldcg(&g_part[(((size_t)bg * 16 + j) * H + n0 + nn) * BPG + bb]);
            }
            if (q > 0) sRed[(q - 1) * 128 + idx] = ssum;
            __syncthreads();
            if (q == 0) {
                float tot = ssum + sRed[idx] + sRed[128 + idx] + sRed[256 + idx] + rkb2;
                float hn = sG[384 + idx] * tanhf(tot);
                __stcg(&g_h[(bg * H + n0 + nn) * BPG + bb], hn);
            }
        }
        gsync_arrive(bg);  tgt += 16;  gsync_wait(bg, tgt);   // barrier 3
    }

    // ---- epilogue: LN of h(T-1) -> out row T-1 (+ final h, c) ----
    {
        {
            const float4* src = (const float4*)(g_h + bg * (H * BPG));
            float4 v = __ldcg(&src[tid]);
            int n = tid >> 1, bo = (tid & 1) * 8;
            *(float4*)&sA2[n * 16 + bo]     = make_float4(v.x, v.x, v.y, v.y);
            *(float4*)&sA2[n * 16 + bo + 4] = make_float4(v.z, v.z, v.w, v.w);
        }
        __syncthreads();
        float s = 0.f, s2 = 0.f;
#pragma unroll
        for (int j = 0; j < 4; j++) {
            int flat = tid + j * 512;
            float v = sA2[(flat >> 3) * 16 + (flat & 7) * 2];
            s += v; s2 += v * v;
        }
        s  += __shfl_xor_sync(0xffffffffu, s, 8);
        s2 += __shfl_xor_sync(0xffffffffu, s2, 8);
        s  += __shfl_xor_sync(0xffffffffu, s, 16);
        s2 += __shfl_xor_sync(0xffffffffu, s2, 16);
        int lane = tid & 31, wp = tid >> 5;
        if (lane < 8) { sSt[wp * 16 + lane * 2] = s; sSt[wp * 16 + lane * 2 + 1] = s2; }
        __syncthreads();
        if (tid < 8) {
            float ss = 0.f, qq = 0.f;
#pragma unroll
            for (int w = 0; w < 16; w++) { ss += sSt[w * 16 + tid * 2]; qq += sSt[w * 16 + tid * 2 + 1]; }
            float mu = ss * invH;
            float var = qq * invH - mu * mu;
            sMu[tid] = mu; sRstd[tid] = rsqrtf(var + EPS);
        }
        __syncthreads();
        if (tid < 128) {
            int bb = tid & 7, nn = tid >> 3;
            float hr = sA2[(n0 + nn) * 16 + bb * 2];
            float hn = (hr - sMu[bb]) * sRstd[bb] * rgam + rbet;
            out[((size_t)(b0 + bb) * T + (T - 1)) * H + n0 + nn] = hn;
            if (has_hc) {
                out[(size_t)B * T * H + (size_t)(b0 + bb) * H + n0 + nn] = hn;
                out[(size_t)B * T * H + (size_t)B * H + (size_t)(b0 + bb) * H + n0 + nn] = sCc[tid];
            }
        }
    }
}

// ---------------- launch ----------------
extern "C" void kernel_launch(void* const* d_in, const int* in_sizes, int n_in,
                              void* d_out, int out_size)
{
    const float* x  = (const float*)d_in[0];
    const float* Wi = (const float*)d_in[1];  const float* bi = (const float*)d_in[2];
    const float* Wf = (const float*)d_in[3];  const float* bf = (const float*)d_in[4];
    const float* Wc = (const float*)d_in[5];  const float* bc = (const float*)d_in[6];
    const float* Wo = (const float*)d_in[7];  const float* bo = (const float*)d_in[8];
    const float* Ui = (const float*)d_in[9];  const float* Uf = (const float*)d_in[10];
    const float* Uc = (const float*)d_in[11]; const float* Uo = (const float*)d_in[12];
    const float* K1 = (const float*)d_in[13]; const float* kb1 = (const float*)d_in[14];
    const float* K2 = (const float*)d_in[15]; const float* kb2 = (const float*)d_in[16];
    const float* gamma = (const float*)d_in[17];
    const float* beta  = (const float*)d_in[18];
    float* out = (float*)d_out;

    const int has_hc = (out_size >= B * T * H + 2 * B * H) ? 1 : 0;

    const int smem_xproj = 2 * 128 * 68 * (int)sizeof(float);
    const int smem_scan  = (16384 + 8192 + 16384 + 4096 + 4608 + 256 + 512 +
                            128 + 8 + 8 + 64 + 64 + 256) * (int)sizeof(float);

    cudaFuncSetAttribute(k_xproj, cudaFuncAttributeMaxDynamicSharedMemorySize, smem_xproj);
    cudaFuncSetAttribute(k_scan,  cudaFuncAttributeMaxDynamicSharedMemorySize, smem_scan);

    k_init<<<1, 256>>>();
    k_xproj<<<dim3(16, T), 256, smem_xproj>>>(x, Wi, Wf, Wc, Wo, bi, bf, bc, bo);
    k_dummy<<<1, 32>>>();   // keeps k_scan on ncu's profiled launch index
    k_scan<<<NCTA, NT, smem_scan>>>(Ui, Uf, Uc, Uo, K1, kb1, K2, kb2,
                                    gamma, beta, out, has_hc);
}

// round 7
// speedup vs baseline: 1.1744x; 1.1744x over previous
#include <cuda_runtime.h>
#include <math.h>
#include <stdint.h>

constexpr int B  = 64;
constexpr int T  = 2048;
constexpr int D  = 128;
constexpr int H  = 256;
constexpr int H2 = 512;
constexpr float EPS = 1e-5f;

constexpr int NCTA = 128;   // 16 col-groups x 8 batch-groups
constexpr int NT   = 512;
constexpr int GR   = 8;     // batch groups
constexpr int BPG  = 8;     // rows per group

// ---------------- device scratch ----------------
__device__ float g_xproj[(size_t)T * GR * 4 * H * BPG]; // [t][bg][g][n][b']
__device__ float g_h[GR * H * BPG];                     // [bg][(n)*8 + b']
__device__ float g_c[GR * H * BPG];
__device__ float g_part[(size_t)GR * 16 * H * BPG];     // [bg][j][n][b']
__device__ unsigned int g_barr[GR * 32];

__global__ void k_init() { if (threadIdx.x < GR * 32) g_barr[threadIdx.x] = 0u; }
__global__ void k_dummy() { }   // ncu launch-index alignment

// ---------------- packed f32x2 helpers (sm_103a) ----------------
__device__ __forceinline__ uint64_t pack2(float v) {
    uint64_t r;
    asm("mov.b64 %0, {%1, %1};" : "=l"(r) : "r"(__float_as_uint(v)));
    return r;
}
__device__ __forceinline__ void ffma2(uint64_t& a, uint64_t x, uint64_t y) {
    asm("fma.rn.f32x2 %0, %1, %2, %0;" : "+l"(a) : "l"(x), "l"(y));
}
__device__ __forceinline__ float2 unpk(uint64_t a) {
    float2 f;
    asm("mov.b64 {%0, %1}, %2;" : "=f"(f.x), "=f"(f.y) : "l"(a));
    return f;
}

// ---------------- phase 1: input-projection GEMM (unchanged) ----------------
__global__ void __launch_bounds__(256) k_xproj(
    const float* __restrict__ x,
    const float* __restrict__ W0, const float* __restrict__ W1,
    const float* __restrict__ W2, const float* __restrict__ W3,
    const float* __restrict__ b0, const float* __restrict__ b1,
    const float* __restrict__ b2, const float* __restrict__ b3)
{
    extern __shared__ float sm[];
    float* As = sm;
    float* Bs = sm + 128 * 68;

    const int tid = threadIdx.x;
    const int t  = blockIdx.y;
    const int nb = blockIdx.x;
    const int g  = nb >> 2;
    const int nbase = (nb & 3) * 64;

    const float* W    = (g == 0) ? W0 : (g == 1) ? W1 : (g == 2) ? W2 : W3;
    const float* bias = (g == 0) ? b0 : (g == 1) ? b1 : (g == 2) ? b2 : b3;

    for (int idx = tid; idx < 64 * 128; idx += 256) {
        int bb = idx >> 7, d = idx & 127;
        As[d * 68 + bb] = x[(size_t)bb * T * D + (size_t)t * D + d];
    }
    for (int idx = tid; idx < 128 * 64; idx += 256) {
        int d = idx >> 6, np = idx & 63;
        Bs[d * 68 + np] = W[(size_t)d * H + nbase + np];
    }
    __syncthreads();

    const int tx = tid & 15, ty = tid >> 4;
    const int bb0 = ty * 4, np0 = tx * 4;

    float acc[4][4];
#pragma unroll
    for (int i = 0; i < 4; i++)
#pragma unroll
        for (int j = 0; j < 4; j++) acc[i][j] = 0.f;

#pragma unroll 8
    for (int k = 0; k < 128; k++) {
        float4 av = *(const float4*)&As[k * 68 + bb0];
        float4 wv = *(const float4*)&Bs[k * 68 + np0];
        acc[0][0] += av.x * wv.x; acc[0][1] += av.x * wv.y; acc[0][2] += av.x * wv.z; acc[0][3] += av.x * wv.w;
        acc[1][0] += av.y * wv.x; acc[1][1] += av.y * wv.y; acc[1][2] += av.y * wv.z; acc[1][3] += av.y * wv.w;
        acc[2][0] += av.z * wv.x; acc[2][1] += av.z * wv.y; acc[2][2] += av.z * wv.z; acc[2][3] += av.z * wv.w;
        acc[3][0] += av.w * wv.x; acc[3][1] += av.w * wv.y; acc[3][2] += av.w * wv.z; acc[3][3] += av.w * wv.w;
    }

#pragma unroll
    for (int j = 0; j < 4; j++) {
        int n = nbase + np0 + j;
        float bv = __ldg(&bias[n]);
#pragma unroll
        for (int i = 0; i < 4; i++) {
            int bb = bb0 + i;
            g_xproj[((((size_t)t * GR + (bb >> 3)) * 4 + g) * H + n) * BPG + (bb & 7)]
                = acc[i][j] + bv;
        }
    }
}

// ---------------- group barrier ----------------
__device__ __forceinline__ void gsync_arrive(int bg)
{
    __syncthreads();
    if (threadIdx.x == 0)
        asm volatile("red.release.gpu.global.add.u32 [%0], 1;"
                     :: "l"(&g_barr[bg * 32]) : "memory");
}
__device__ __forceinline__ void gsync_wait(int bg, unsigned int tgt)
{
    if (threadIdx.x < 32) {
        unsigned int v;
        do {
            asm volatile("ld.acquire.gpu.global.u32 %0, [%1];"
                         : "=r"(v) : "l"(&g_barr[bg * 32]) : "memory");
        } while (v < tgt);
    }
    __syncthreads();
}

__device__ __forceinline__ float sigf(float v) { return 1.f / (1.f + expf(-v)); }

// ---------------- phase 2: persistent scan (register weights + broadcast LDS) --
__global__ void __launch_bounds__(NT, 1) k_scan(
    const float* __restrict__ Ui, const float* __restrict__ Uf,
    const float* __restrict__ Uc, const float* __restrict__ Uo,
    const float* __restrict__ K1, const float* __restrict__ kb1,
    const float* __restrict__ K2, const float* __restrict__ kb2,
    const float* __restrict__ gamma, const float* __restrict__ beta,
    float* __restrict__ out, int has_hc)
{
    extern __shared__ float sm[];
    float* sAct = sm;             // 2048 activation staging [k*8+b]
    float* sRed = sAct + 2048;    // 4608 split-K partials
    float* sZp  = sRed + 4608;    //  256 z pair-interleaved [m'][8]
    float* sG   = sZp + 256;      //  512 gates [g][n'*8+b]
    float* sCc  = sG  + 512;      //  128 cell state
    float* sMu  = sCc + 128;      //    8
    float* sRstd= sMu + 8;        //    8
    float* sGU  = sRstd + 8;      //   64 sum_k gamma*U per (n',g)
    float* sBU  = sGU + 64;       //   64 sum_k beta*U
    float* sSt  = sBU + 64;       //  256 stats partials [16w][16]

    const int tid = threadIdx.x;
    const int cta = blockIdx.x;
    const int cg  = cta & 15;
    const int bg  = cta >> 4;
    const int n0  = cg * 16;
    const int m0  = cg * 32;
    const int b0  = bg * 8;

    // ---- P1 producer role: chunk = tid>>6 (8 x 32k), col q = tid&63 -> (n,g)
    const int p1q     = tid & 63;
    const int p1n     = p1q >> 2;
    const int p1g     = p1q & 3;
    const int p1chunk = tid >> 6;
    // ---- P2 producer role: chunk = tid>>5 (16 x 16k), col m' = tid&31
    const int p2m     = tid & 31;
    const int p2chunk = tid >> 5;
    // ---- P3 producer role: n = tid&255 (absolute), mh = tid>>8 (2 x 16m)
    const int p3n     = tid & 255;
    const int p3mh    = tid >> 8;
    // ---- gate consumer role
    const int xg  = tid >> 7;          // gate 0..3
    const int xrn = (tid >> 3) & 15;   // n'
    const int xrb = tid & 7;           // b'

    // ---- weights into registers (persist across all timesteps) ----
    float wU[32], wK1[16], wK2[16];
    {
        const float* Up = (p1g == 0) ? Ui : (p1g == 1) ? Uf : (p1g == 2) ? Uc : Uo;
#pragma unroll
        for (int kk = 0; kk < 32; kk++) {
            int k = p1chunk * 32 + kk;
            wU[kk] = __ldg(&gamma[k]) * __ldg(&Up[(size_t)k * H + n0 + p1n]);
        }
#pragma unroll
        for (int kk = 0; kk < 16; kk++) {
            int k = p2chunk * 16 + kk;
            wK1[kk] = __ldg(&K1[(size_t)k * H2 + m0 + p2m]);
        }
#pragma unroll
        for (int mm = 0; mm < 16; mm++) {
            int m = m0 + p3mh * 16 + mm;
            wK2[mm] = __ldg(&K2[(size_t)m * H + p3n]);
        }
    }

    if (tid < 128) sCc[tid] = 0.f;
    if (tid < 64) {
        int n = tid >> 2, g = tid & 3;
        const float* Up = (g == 0) ? Ui : (g == 1) ? Uf : (g == 2) ? Uc : Uo;
        float s = 0.f, bs = 0.f;
        for (int k = 0; k < H; k++) {
            float u = __ldg(&Up[(size_t)k * H + n0 + n]);
            s  += __ldg(&gamma[k]) * u;
            bs += __ldg(&beta[k])  * u;
        }
        sGU[tid] = s; sBU[tid] = bs;
    }
    float rkb1 = 0.f;
    if (tid < 256) rkb1 = kb1[m0 + (tid >> 3)];
    float rkb2 = 0.f, rgam = 0.f, rbet = 0.f;
    if (tid < 128) {
        rkb2 = kb2[n0 + (tid >> 3)];
        rgam = gamma[n0 + (tid >> 3)];
        rbet = beta[n0 + (tid >> 3)];
    }
    __syncthreads();

    unsigned int tgt = 0;
    const float invH = 1.f / (float)H;

    float xp = g_xproj[(((size_t)0 * GR + bg) * 4 + xg) * (H * BPG)
                       + (size_t)(n0 + xrn) * BPG + xrb];

    for (int t = 0; t < T; t++) {
        float outv = 0.f;
        if (t > 0) {
            // ---- stage h flat [k*8+b] (L2-direct float4) ----
            {
                const float4* src = (const float4*)(g_h + bg * (H * BPG));
                *(float4*)&sAct[tid * 4] = __ldcg(&src[tid]);
            }
            __syncthreads();
            // ---- LN stats ----
            {
                float s = 0.f, s2 = 0.f;
#pragma unroll
                for (int j = 0; j < 4; j++) {
                    float v = sAct[tid + j * 512];
                    s += v; s2 += v * v;
                }
                s  += __shfl_xor_sync(0xffffffffu, s, 8);
                s2 += __shfl_xor_sync(0xffffffffu, s2, 8);
                s  += __shfl_xor_sync(0xffffffffu, s, 16);
                s2 += __shfl_xor_sync(0xffffffffu, s2, 16);
                int lane = tid & 31, wp = tid >> 5;
                if (lane < 8) { sSt[wp * 16 + lane * 2] = s; sSt[wp * 16 + lane * 2 + 1] = s2; }
            }
            __syncthreads();
            if (tid < 8) {
                float ss = 0.f, qq = 0.f;
#pragma unroll
                for (int w = 0; w < 16; w++) { ss += sSt[w * 16 + tid * 2]; qq += sSt[w * 16 + tid * 2 + 1]; }
                float mu = ss * invH;
                float var = qq * invH - mu * mu;
                sMu[tid] = mu; sRstd[tid] = rsqrtf(var + EPS);
            }
            __syncthreads();
            if (tid < 128) {   // LN'd output; STG deferred past arrive
                int bb = tid & 7, nn = tid >> 3;
                outv = (sAct[(n0 + nn) * 8 + bb] - sMu[bb]) * sRstd[bb] * rgam + rbet;
            }

            // ---- P1: recurrent GEMV, reg weights + broadcast h ----
            {
                uint64_t A0 = 0, A1 = 0, A2 = 0, A3 = 0;
                const int kb = p1chunk * 32;
#pragma unroll
                for (int kk = 0; kk < 32; kk++) {
                    const float* hp = &sAct[(kb + kk) * 8];
                    ulonglong2 pa = *(const ulonglong2*)hp;        // (b0,b1),(b2,b3)
                    ulonglong2 pb = *(const ulonglong2*)(hp + 4);  // (b4,b5),(b6,b7)
                    uint64_t W = pack2(wU[kk]);
                    ffma2(A0, pa.x, W); ffma2(A1, pa.y, W);
                    ffma2(A2, pb.x, W); ffma2(A3, pb.y, W);
                }
                int base = p1chunk * 576 + p1q * 9;
                float2 f;
                f = unpk(A0); sRed[base + 0] = f.x; sRed[base + 1] = f.y;
                f = unpk(A1); sRed[base + 2] = f.x; sRed[base + 3] = f.y;
                f = unpk(A2); sRed[base + 4] = f.x; sRed[base + 5] = f.y;
                f = unpk(A3); sRed[base + 6] = f.x; sRed[base + 7] = f.y;
            }
            __syncthreads();
        }

        // ---- gate consumer: one gate value per thread ----
        {
            float pa;
            int q = xrn * 4 + xg;
            if (t > 0) {
                float d = 0.f;
#pragma unroll
                for (int c = 0; c < 8; c++) d += sRed[c * 576 + q * 9 + xrb];
                float mu = sMu[xrb], rs = sRstd[xrb];
                pa = xp + rs * (d - mu * sGU[q]) + sBU[q];
            } else pa = xp;
            float v = (xg == 2) ? tanhf(pa) : sigf(pa);
            sG[xg * 128 + xrn * 8 + xrb] = v;
        }
        __syncthreads();
        if (tid < 128) {  // c update
            float cn = sG[128 + tid] * sCc[tid] + sG[tid] * sG[256 + tid];
            sCc[tid] = cn;
            __stcg(&g_c[bg * (H * BPG) + (n0 + (tid >> 3)) * BPG + (tid & 7)], cn);
        }
        gsync_arrive(bg);                 // barrier 1 arrive: c visible
        if (t > 0 && tid < 128) {
            int bb = tid & 7, nn = tid >> 3;
            out[((size_t)(b0 + bb) * T + (t - 1)) * H + n0 + nn] = outv;
        }
        if (t + 1 < T)
            xp = g_xproj[(((size_t)(t + 1) * GR + bg) * 4 + xg) * (H * BPG)
                         + (size_t)(n0 + xrn) * BPG + xrb];
        tgt += 16;
        gsync_wait(bg, tgt);

        // ---- stage c flat ----
        {
            const float4* src = (const float4*)(g_c + bg * (H * BPG));
            *(float4*)&sAct[tid * 4] = __ldcg(&src[tid]);
        }
        __syncthreads();

        // ---- P2: z = tanh(c @ K1 + kb1), reg weights + broadcast c ----
        {
            uint64_t A0 = 0, A1 = 0, A2 = 0, A3 = 0;
            const int kb = p2chunk * 16;
#pragma unroll
            for (int kk = 0; kk < 16; kk++) {
                const float* cp = &sAct[(kb + kk) * 8];
                ulonglong2 pa = *(const ulonglong2*)cp;
                ulonglong2 pb = *(const ulonglong2*)(cp + 4);
                uint64_t W = pack2(wK1[kk]);
                ffma2(A0, pa.x, W); ffma2(A1, pa.y, W);
                ffma2(A2, pb.x, W); ffma2(A3, pb.y, W);
            }
            int base = p2chunk * 288 + p2m * 9;
            float2 f;
            f = unpk(A0); sRed[base + 0] = f.x; sRed[base + 1] = f.y;
            f = unpk(A1); sRed[base + 2] = f.x; sRed[base + 3] = f.y;
            f = unpk(A2); sRed[base + 4] = f.x; sRed[base + 5] = f.y;
            f = unpk(A3); sRed[base + 6] = f.x; sRed[base + 7] = f.y;
        }
        __syncthreads();
        if (tid < 256) {   // z consumer -> pair-interleaved sZp
            int mq = tid >> 3, bb = tid & 7;
            float d = 0.f;
#pragma unroll
            for (int c = 0; c < 16; c++) d += sRed[c * 288 + mq * 9 + bb];
            sZp[mq * 8 + (bb & 3) * 2 + (bb >> 2)] = tanhf(d + rkb1);
        }
        __syncthreads();

        // ---- P3 producer: partial ctr, reg weights + broadcast z ----
        float2 f0, f1, f2, f3;
        {
            uint64_t A0 = 0, A1 = 0, A2 = 0, A3 = 0;
#pragma unroll
            for (int mm = 0; mm < 16; mm++) {
                const float* zp = &sZp[(p3mh * 16 + mm) * 8];
                ulonglong2 pa = *(const ulonglong2*)zp;        // (b0,b4),(b1,b5)
                ulonglong2 pb = *(const ulonglong2*)(zp + 4);  // (b2,b6),(b3,b7)
                uint64_t W = pack2(wK2[mm]);
                ffma2(A0, pa.x, W); ffma2(A1, pa.y, W);
                ffma2(A2, pb.x, W); ffma2(A3, pb.y, W);
            }
            f0 = unpk(A0); f1 = unpk(A1); f2 = unpk(A2); f3 = unpk(A3);
            if (p3mh == 1) {
                int base = p3n * 9;
                sRed[base + 0] = f0.x; sRed[base + 1] = f1.x; sRed[base + 2] = f2.x; sRed[base + 3] = f3.x;
                sRed[base + 4] = f0.y; sRed[base + 5] = f1.y; sRed[base + 6] = f2.y; sRed[base + 7] = f3.y;
            }
        }
        __syncthreads();
        if (tid < 256) {   // combine halves, write partial tile
            int base = p3n * 9;
            float4 lo = make_float4(f0.x + sRed[base + 0], f1.x + sRed[base + 1],
                                    f2.x + sRed[base + 2], f3.x + sRed[base + 3]);
            float4 hi = make_float4(f0.y + sRed[base + 4], f1.y + sRed[base + 5],
                                    f2.y + sRed[base + 6], f3.y + sRed[base + 7]);
            float* gp = &g_part[(((size_t)bg * 16 + cg) * H + p3n) * BPG];
            __stcg((float4*)gp, lo);
            __stcg((float4*)(gp + 4), hi);
        }
        gsync_arrive(bg);  tgt += 16;  gsync_wait(bg, tgt);   // barrier 2

        // ---- P3 consumer ----
        {
            int idx = tid & 127, q = tid >> 7;
            int nn = idx >> 3, bb = idx & 7;
            float ssum = 0.f;
#pragma unroll
            for (int jj = 0; jj < 4; jj++) {
                int j = q * 4 + jj;
                ssum += __ldcg(&g_part[(((size_t)bg * 16 + j) * H + n0 + nn) * BPG + bb]);
            }
            if (q > 0) sRed[(q - 1) * 128 + idx] = ssum;
            __syncthreads();
            if (q == 0) {
                float tot = ssum + sRed[idx] + sRed[128 + idx] + sRed[256 + idx] + rkb2;
                float hn = sG[384 + idx] * tanhf(tot);
                __stcg(&g_h[bg * (H * BPG) + (n0 + nn) * BPG + bb], hn);
            }
        }
        gsync_arrive(bg);  tgt += 16;  gsync_wait(bg, tgt);   // barrier 3
    }

    // ---- epilogue: LN of h(T-1) ----
    {
        {
            const float4* src = (const float4*)(g_h + bg * (H * BPG));
            *(float4*)&sAct[tid * 4] = __ldcg(&src[tid]);
        }
        __syncthreads();
        float s = 0.f, s2 = 0.f;
#pragma unroll
        for (int j = 0; j < 4; j++) {
            float v = sAct[tid + j * 512];
            s += v; s2 += v * v;
        }
        s  += __shfl_xor_sync(0xffffffffu, s, 8);
        s2 += __shfl_xor_sync(0xffffffffu, s2, 8);
        s  += __shfl_xor_sync(0xffffffffu, s, 16);
        s2 += __shfl_xor_sync(0xffffffffu, s2, 16);
        int lane = tid & 31, wp = tid >> 5;
        if (lane < 8) { sSt[wp * 16 + lane * 2] = s; sSt[wp * 16 + lane * 2 + 1] = s2; }
        __syncthreads();
        if (tid < 8) {
            float ss = 0.f, qq = 0.f;
#pragma unroll
            for (int w = 0; w < 16; w++) { ss += sSt[w * 16 + tid * 2]; qq += sSt[w * 16 + tid * 2 + 1]; }
            float mu = ss * invH;
            float var = qq * invH - mu * mu;
            sMu[tid] = mu; sRstd[tid] = rsqrtf(var + EPS);
        }
        __syncthreads();
        if (tid < 128) {
            int bb = tid & 7, nn = tid >> 3;
            float hr = sAct[(n0 + nn) * 8 + bb];
            float hn = (hr - sMu[bb]) * sRstd[bb] * rgam + rbet;
            out[((size_t)(b0 + bb) * T + (T - 1)) * H + n0 + nn] = hn;
            if (has_hc) {
                out[(size_t)B * T * H + (size_t)(b0 + bb) * H + n0 + nn] = hn;
                out[(size_t)B * T * H + (size_t)B * H + (size_t)(b0 + bb) * H + n0 + nn] = sCc[tid];
            }
        }
    }
}

// ---------------- launch ----------------
extern "C" void kernel_launch(void* const* d_in, const int* in_sizes, int n_in,
                              void* d_out, int out_size)
{
    const float* x  = (const float*)d_in[0];
    const float* Wi = (const float*)d_in[1];  const float* bi = (const float*)d_in[2];
    const float* Wf = (const float*)d_in[3];  const float* bf = (const float*)d_in[4];
    const float* Wc = (const float*)d_in[5];  const float* bc = (const float*)d_in[6];
    const float* Wo = (const float*)d_in[7];  const float* bo = (const float*)d_in[8];
    const float* Ui = (const float*)d_in[9];  const float* Uf = (const float*)d_in[10];
    const float* Uc = (const float*)d_in[11]; const float* Uo = (const float*)d_in[12];
    const float* K1 = (const float*)d_in[13]; const float* kb1 = (const float*)d_in[14];
    const float* K2 = (const float*)d_in[15]; const float* kb2 = (const float*)d_in[16];
    const float* gamma = (const float*)d_in[17];
    const float* beta  = (const float*)d_in[18];
    float* out = (float*)d_out;

    const int has_hc = (out_size >= B * T * H + 2 * B * H) ? 1 : 0;

    const int smem_xproj = 2 * 128 * 68 * (int)sizeof(float);
    // actual use ~32KB; pad to 120KB to force 1 CTA/SM (keeps 128 CTAs spread)
    const int smem_scan  = 120 * 1024;

    cudaFuncSetAttribute(k_xproj, cudaFuncAttributeMaxDynamicSharedMemorySize, smem_xproj);
    cudaFuncSetAttribute(k_scan,  cudaFuncAttributeMaxDynamicSharedMemorySize, smem_scan);

    k_init<<<1, 256>>>();
    k_xproj<<<dim3(16, T), 256, smem_xproj>>>(x, Wi, Wf, Wc, Wo, bi, bf, bc, bo);
    k_dummy<<<1, 32>>>();   // keeps k_scan on ncu's profiled launch index
    k_scan<<<NCTA, NT, smem_scan>>>(Ui, Uf, Uc, Uo, K1, kb1, K2, kb2,
                                    gamma, beta, out, has_hc);
}